// round 17
// baseline (speedup 1.0000x reference)
#include <cuda_runtime.h>
#include <cuda_bf16.h>
#include <math.h>

#define N_AGENTS 8192
#define OBS_D    520
#define EMB      64
#define HID      128
#define NACT     6
#define NSPLIT   16
#define SST      68          // smem row stride (== 4 mod 32: frag loads conflict-free)

// fp32 -> tf32 (round to nearest) as b32 bit pattern
__device__ __forceinline__ unsigned t32(float x) {
    unsigned r;
    asm("cvt.rna.tf32.f32 %0, %1;" : "=r"(r) : "f"(x));
    return r;
}
__device__ __forceinline__ float t32f(float x) {
    return __uint_as_float(t32(x));
}

// m16n8k8 tf32 mma, D/C fp32 accumulate
__device__ __forceinline__ void mma8(float4& d, unsigned a0, unsigned a1,
                                     unsigned a2, unsigned a3,
                                     unsigned b0, unsigned b1) {
    asm("mma.sync.aligned.m16n8k8.row.col.f32.tf32.tf32.f32 "
        "{%0,%1,%2,%3}, {%4,%5,%6,%7}, {%8,%9}, {%0,%1,%2,%3};"
        : "+f"(d.x), "+f"(d.y), "+f"(d.z), "+f"(d.w)
        : "r"(a0), "r"(a1), "r"(a2), "r"(a3), "r"(b0), "r"(b1));
}

// ---------------- scratch (__device__ globals: no allocations allowed) ----------
__device__ float g_h1   [N_AGENTS * EMB];
__device__ float g_bp   [N_AGENTS * EMB];
__device__ float g_cat  [N_AGENTS * HID];
__device__ float g_gruin[N_AGENTS * HID];
__device__ float g_r    [N_AGENTS * HID];
__device__ float g_z    [N_AGENTS * HID];
__device__ float g_gn   [N_AGENTS * HID];
__device__ float g_hn   [N_AGENTS * HID];
__device__ float g_Opart[NSPLIT * N_AGENTS * EMB];
__device__ float g_lpart[NSPLIT * N_AGENTS];

// =================================================================
// 3xTF32 tensor-core GEMM: C = act(A1@W1 (+A2@W2) + bias)
// CTA = 64 rows x 64 cols, 8 warps (4 row-groups x 2 col-groups).
// A row-major [M][K], W row-major [K][N]. K chunked by 64, zero-padded.
// hi/lo split restores ~fp32 accuracy: C += Ah*Bh + Ah*Bl + Al*Bh.
// ACT: 0 none, 1 relu, 2 sigmoid. Dyn smem: 4 x 64 x SST floats (~68 KB).
// =================================================================
template<int ACT>
__global__ __launch_bounds__(256, 2)
void gemm3_kernel(const float* __restrict__ A1, int lda1,
                  const float* __restrict__ W1, int ldw1, int K1,
                  const float* __restrict__ A2, int lda2,
                  const float* __restrict__ W2, int ldw2, int K2,
                  const float* __restrict__ bias,
                  float* __restrict__ C, int ldc)
{
    extern __shared__ float sm[];
    float* sAh = sm;                 // [64][SST] A-hi
    float* sAl = sm +  64 * SST;     // [64][SST] A-lo
    float* sWh = sm + 128 * SST;     // [n][k] W-hi (transposed)
    float* sWl = sm + 192 * SST;     // [n][k] W-lo

    const int t    = threadIdx.x;
    const int w    = t >> 5;
    const int lane = t & 31;
    const int rg   = w & 3;          // row-group: rows 16*rg..16*rg+15
    const int cg   = w >> 2;         // col-group: cols 32*cg..32*cg+31
    const int g    = lane >> 2;
    const int tq   = lane & 3;
    const int m0   = blockIdx.x * 64;
    const int n0   = blockIdx.y * 64;

    float4 Cf[4];
#pragma unroll
    for (int j = 0; j < 4; j++) Cf[j] = make_float4(0.f, 0.f, 0.f, 0.f);

    const int arow = (16 * rg + g) * SST + tq;
    const int brow = (32 * cg + g) * SST + tq;

    const int nsrc = (A2 != nullptr) ? 2 : 1;
    for (int src = 0; src < nsrc; src++) {
        const float* A = src ? A2 : A1;
        const float* W = src ? W2 : W1;
        const int lda  = src ? lda2 : lda1;
        const int ldw  = src ? ldw2 : ldw1;
        const int K    = src ? K2  : K1;

        for (int kc0 = 0; kc0 < K; kc0 += 64) {
            const int KC = min(64, K - kc0);      // multiple of 4 for our shapes
            const int q4 = KC >> 2;
            __syncthreads();
            // ---- A chunk [64 x KC] -> hi/lo tiles (zero-padded to 64) ----
#pragma unroll
            for (int s = 0; s < 4; s++) {
                int i = t + 256 * s;
                int r = i >> 4, c = i & 15;
                float4 h4 = make_float4(0.f, 0.f, 0.f, 0.f);
                float4 l4 = make_float4(0.f, 0.f, 0.f, 0.f);
                if (c < q4) {
                    float4 v = *(const float4*)(A + (long)(m0 + r) * lda + kc0 + 4 * c);
                    h4.x = t32f(v.x); l4.x = t32f(v.x - h4.x);
                    h4.y = t32f(v.y); l4.y = t32f(v.y - h4.y);
                    h4.z = t32f(v.z); l4.z = t32f(v.z - h4.z);
                    h4.w = t32f(v.w); l4.w = t32f(v.w - h4.w);
                }
                *(float4*)(sAh + r * SST + 4 * c) = h4;
                *(float4*)(sAl + r * SST + 4 * c) = l4;
            }
            // ---- W chunk [KC x 64] -> transposed hi/lo [n][k] (zero-padded) ----
#pragma unroll
            for (int s = 0; s < 4; s++) {
                int i = t + 256 * s;
                int k = i >> 4, c = i & 15;
                float4 h4 = make_float4(0.f, 0.f, 0.f, 0.f);
                float4 l4 = make_float4(0.f, 0.f, 0.f, 0.f);
                if (k < KC) {
                    float4 v = *(const float4*)(W + (long)(kc0 + k) * ldw + n0 + 4 * c);
                    h4.x = t32f(v.x); l4.x = t32f(v.x - h4.x);
                    h4.y = t32f(v.y); l4.y = t32f(v.y - h4.y);
                    h4.z = t32f(v.z); l4.z = t32f(v.z - h4.z);
                    h4.w = t32f(v.w); l4.w = t32f(v.w - h4.w);
                }
                sWh[(4 * c + 0) * SST + k] = h4.x;
                sWh[(4 * c + 1) * SST + k] = h4.y;
                sWh[(4 * c + 2) * SST + k] = h4.z;
                sWh[(4 * c + 3) * SST + k] = h4.w;
                sWl[(4 * c + 0) * SST + k] = l4.x;
                sWl[(4 * c + 1) * SST + k] = l4.y;
                sWl[(4 * c + 2) * SST + k] = l4.z;
                sWl[(4 * c + 3) * SST + k] = l4.w;
            }
            __syncthreads();

            // ---- mainloop: 8 ks steps, 4 n-tiles, 3 mmas each ----
#pragma unroll
            for (int ks = 0; ks < 8; ks++) {
                unsigned ah0 = __float_as_uint(sAh[arow       + 8 * ks]);
                unsigned ah1 = __float_as_uint(sAh[arow + 8 * SST + 8 * ks]);
                unsigned ah2 = __float_as_uint(sAh[arow       + 8 * ks + 4]);
                unsigned ah3 = __float_as_uint(sAh[arow + 8 * SST + 8 * ks + 4]);
                unsigned al0 = __float_as_uint(sAl[arow       + 8 * ks]);
                unsigned al1 = __float_as_uint(sAl[arow + 8 * SST + 8 * ks]);
                unsigned al2 = __float_as_uint(sAl[arow       + 8 * ks + 4]);
                unsigned al3 = __float_as_uint(sAl[arow + 8 * SST + 8 * ks + 4]);
#pragma unroll
                for (int j = 0; j < 4; j++) {
                    int bb = brow + j * 8 * SST + 8 * ks;
                    unsigned bh0 = __float_as_uint(sWh[bb]);
                    unsigned bh1 = __float_as_uint(sWh[bb + 4]);
                    unsigned bl0 = __float_as_uint(sWl[bb]);
                    unsigned bl1 = __float_as_uint(sWl[bb + 4]);
                    mma8(Cf[j], ah0, ah1, ah2, ah3, bh0, bh1);
                    mma8(Cf[j], ah0, ah1, ah2, ah3, bl0, bl1);
                    mma8(Cf[j], al0, al1, al2, al3, bh0, bh1);
                }
            }
        }
    }

    // ---- epilogue: bias + activation + store ----
    const int row0 = m0 + 16 * rg + g;
#pragma unroll
    for (int j = 0; j < 4; j++) {
        int col = n0 + 32 * cg + 8 * j + 2 * tq;
        float bx = 0.f, by = 0.f;
        if (bias) { bx = bias[col]; by = bias[col + 1]; }
        float v0 = Cf[j].x + bx, v1 = Cf[j].y + by;
        float v2 = Cf[j].z + bx, v3 = Cf[j].w + by;
        if (ACT == 1) {
            v0 = fmaxf(v0, 0.f); v1 = fmaxf(v1, 0.f);
            v2 = fmaxf(v2, 0.f); v3 = fmaxf(v3, 0.f);
        }
        if (ACT == 2) {
            v0 = 1.f / (1.f + __expf(-v0)); v1 = 1.f / (1.f + __expf(-v1));
            v2 = 1.f / (1.f + __expf(-v2)); v3 = 1.f / (1.f + __expf(-v3));
        }
        *(float2*)(C + (long)row0 * ldc + col)       = make_float2(v0, v1);
        *(float2*)(C + (long)(row0 + 8) * ldc + col) = make_float2(v2, v3);
    }
}

// =================================================================
// tf32 tensor-core flash attention partial (no max-tracking; logits
// bounded ~2). CTA = 128 queries x 8 warps; warp w owns rows 16w..16w+15
// of S and O => P smem round-trip is warp-private (syncwarp only).
// Key tiles of 64, 1/NSPLIT of keys per CTA. Q pre-scaled by 1/8.
// smem: sQ[128x68] sK[64x68] sVt[64x68] sP[128x68] = 102 KB dynamic.
// =================================================================
__global__ __launch_bounds__(256, 2)
void attn_kernel(const float* __restrict__ bp,
                 float* __restrict__ Opart,
                 float* __restrict__ lpart)
{
    extern __shared__ float smx[];
    float* sQ  = smx;                    // [128][SST]
    float* sK  = smx + 128 * SST;        // [64][SST]  (QK B-operand: K)
    float* sVt = sK  + 64 * SST;         // [64][SST]  (PV B-operand: V^T, [d][key])
    float* sP  = sVt + 64 * SST;         // [128][SST] (PV A-operand, parity-XOR cols)

    const int t    = threadIdx.x;
    const int w    = t >> 5;
    const int lane = t & 31;
    const int g    = lane >> 2;          // fragment group id
    const int tq   = lane & 3;           // fragment thread-in-group
    const int kx2  = 2 * (g & 1);        // sP column-parity xor (in 8-col tiles)

    const int qg0   = blockIdx.x * 128;
    const int split = blockIdx.y;

    const int lr = t >> 4;               // loader row (0..15)
    const int lc = t & 15;               // loader col chunk

    // ---- load Q tile 128x64: scale by 1/8, cvt tf32, stride SST ----
#pragma unroll
    for (int s = 0; s < 8; s++) {
        int idx = t + 256 * s;
        int r = idx >> 4, c = idx & 15;
        float4 v = *(const float4*)(bp + (long)(qg0 + r) * 64 + 4 * c);
        float4 o4;
        o4.x = t32f(v.x * 0.125f);
        o4.y = t32f(v.y * 0.125f);
        o4.z = t32f(v.z * 0.125f);
        o4.w = t32f(v.w * 0.125f);
        *(float4*)(sQ + r * SST + 4 * c) = o4;
    }

    float4 Of[8];
#pragma unroll
    for (int nt = 0; nt < 8; nt++) Of[nt] = make_float4(0.f, 0.f, 0.f, 0.f);
    float l0 = 0.0f, l1 = 0.0f;

    const int arow = (16 * w + g) * SST + tq;   // A-frag base (sQ / sP)
    const int brow = g * SST + tq;              // B-frag base (sK / sVt)

    for (int kt = 0; kt < 8; kt++) {
        const int kg0 = (split * 8 + kt) * 64;

        // prefetch K tile (64x64) into regs, off the barrier critical path
        float4 vf[4];
#pragma unroll
        for (int s = 0; s < 4; s++)
            vf[s] = *(const float4*)(bp + (long)(kg0 + lr + 16 * s) * 64 + 4 * lc);

        __syncthreads();   // prev iteration's QK/PV done with sK/sVt
#pragma unroll
        for (int s = 0; s < 4; s++) {
            int r = lr + 16 * s;
            float4 o4;
            o4.x = t32f(vf[s].x);
            o4.y = t32f(vf[s].y);
            o4.z = t32f(vf[s].z);
            o4.w = t32f(vf[s].w);
            *(float4*)(sK + r * SST + 4 * lc) = o4;
            sVt[(4 * lc + 0) * SST + r] = o4.x;
            sVt[(4 * lc + 1) * SST + r] = o4.y;
            sVt[(4 * lc + 2) * SST + r] = o4.z;
            sVt[(4 * lc + 3) * SST + r] = o4.w;
        }
        __syncthreads();

        // ---- S = Qs @ K^T : 8 n-tiles x 8 k-steps of m16n8k8 ----
        float4 Sf[8];
#pragma unroll
        for (int nt = 0; nt < 8; nt++) Sf[nt] = make_float4(0.f, 0.f, 0.f, 0.f);

#pragma unroll
        for (int ks = 0; ks < 8; ks++) {
            unsigned a0 = __float_as_uint(sQ[arow       + 8 * ks]);
            unsigned a1 = __float_as_uint(sQ[arow + 544 + 8 * ks]);      // +8 rows
            unsigned a2 = __float_as_uint(sQ[arow       + 8 * ks + 4]);
            unsigned a3 = __float_as_uint(sQ[arow + 544 + 8 * ks + 4]);
#pragma unroll
            for (int nt = 0; nt < 8; nt++) {
                unsigned b0 = __float_as_uint(sK[brow + 544 * nt + 8 * ks]);
                unsigned b1 = __float_as_uint(sK[brow + 544 * nt + 8 * ks + 4]);
                mma8(Sf[nt], a0, a1, a2, a3, b0, b1);
            }
        }

        // diagonal mask (only tiles overlapping the query range)
        if (kg0 == qg0 || kg0 == qg0 + 64) {
            int r0 = qg0 + 16 * w + g, r1 = r0 + 8;
#pragma unroll
            for (int nt = 0; nt < 8; nt++) {
                int c0 = kg0 + 8 * nt + 2 * tq;
                if (r0 == c0)     Sf[nt].x = -1e4f;
                if (r0 == c0 + 1) Sf[nt].y = -1e4f;
                if (r1 == c0)     Sf[nt].z = -1e4f;
                if (r1 == c0 + 1) Sf[nt].w = -1e4f;
            }
        }

        // ---- P = exp(S) (no max subtraction), l accumulation, store sP ----
#pragma unroll
        for (int nt = 0; nt < 8; nt++) {
            float px = t32f(__expf(Sf[nt].x));
            float py = t32f(__expf(Sf[nt].y));
            float pz = t32f(__expf(Sf[nt].z));
            float pw = t32f(__expf(Sf[nt].w));
            l0 += px + py;
            l1 += pz + pw;
            int pc = 8 * (nt ^ kx2) + 2 * tq;    // parity-XOR column placement
            *(float2*)(sP + (16 * w + g)     * SST + pc) = make_float2(px, py);
            *(float2*)(sP + (16 * w + g + 8) * SST + pc) = make_float2(pz, pw);
        }
        __syncwarp();   // sP rows are warp-private

        // ---- O += P @ V : A from sP (xor-reindexed ks), B from sVt ----
#pragma unroll
        for (int ks = 0; ks < 8; ks++) {
            int ca = 8 * (ks ^ kx2);
            unsigned a0 = __float_as_uint(sP[arow       + ca]);
            unsigned a1 = __float_as_uint(sP[arow + 544 + ca]);
            unsigned a2 = __float_as_uint(sP[arow       + ca + 4]);
            unsigned a3 = __float_as_uint(sP[arow + 544 + ca + 4]);
#pragma unroll
            for (int nt = 0; nt < 8; nt++) {
                unsigned b0 = __float_as_uint(sVt[brow + 544 * nt + 8 * ks]);
                unsigned b1 = __float_as_uint(sVt[brow + 544 * nt + 8 * ks + 4]);
                mma8(Of[nt], a0, a1, a2, a3, b0, b1);
            }
        }
    }

    // ---- epilogue: l quad-reduce, write partials ----
    l0 += __shfl_xor_sync(0xffffffffu, l0, 1);
    l0 += __shfl_xor_sync(0xffffffffu, l0, 2);
    l1 += __shfl_xor_sync(0xffffffffu, l1, 1);
    l1 += __shfl_xor_sync(0xffffffffu, l1, 2);

    const long pbase = (long)split * N_AGENTS;
    const int r0 = qg0 + 16 * w + g;
    if (tq == 0) {
        lpart[pbase + r0]     = l0;
        lpart[pbase + r0 + 8] = l1;
    }
#pragma unroll
    for (int nt = 0; nt < 8; nt++) {
        *(float2*)(Opart + (pbase + r0)     * EMB + 8 * nt + 2 * tq) =
            make_float2(Of[nt].x, Of[nt].y);
        *(float2*)(Opart + (pbase + r0 + 8) * EMB + 8 * nt + 2 * tq) =
            make_float2(Of[nt].z, Of[nt].w);
    }
}

// merge NSPLIT partials into ctx (g_cat cols 64..127): plain sums
__global__ __launch_bounds__(256)
void attn_merge_kernel(const float* __restrict__ Opart,
                       const float* __restrict__ lpart,
                       float* __restrict__ cat_out)
{
    int idx = blockIdx.x * 256 + threadIdx.x;   // over 8192*64
    int row = idx >> 6, col = idx & 63;
    float l = 0.0f, o = 0.0f;
#pragma unroll
    for (int s = 0; s < NSPLIT; s++) {
        l += lpart[s * N_AGENTS + row];
        o += Opart[((long)s * N_AGENTS + row) * EMB + col];
    }
    cat_out[(long)row * HID + EMB + col] = o / l;
}

// =================================================================
// Combine: n = tanh(gn + r*hn); nb = (1-z)*n + z*bel;
// out = [logits (8192x6) | new_beliefs (8192x128)]
// =================================================================
__global__ __launch_bounds__(256)
void combine_kernel(const float* __restrict__ gn, const float* __restrict__ hn,
                    const float* __restrict__ rr, const float* __restrict__ zz,
                    const float* __restrict__ bel,
                    const float* __restrict__ Wout, const float* __restrict__ bout,
                    float* __restrict__ out)
{
    __shared__ float snb[2 * HID];
    const int t = threadIdx.x;
    const int aloc = t >> 7;
    const int k = t & 127;
    const long a = (long)blockIdx.x * 2 + aloc;
    const long idx = a * HID + k;

    float r = rr[idx], z = zz[idx];
    float n = tanhf(gn[idx] + r * hn[idx]);
    float nb = (1.0f - z) * n + z * bel[idx];
    out[(long)N_AGENTS * NACT + idx] = nb;
    snb[aloc * HID + k] = nb;
    __syncthreads();

    if (t < 2 * NACT) {
        int al = t / NACT, j = t - al * NACT;
        float s = bout[j];
#pragma unroll 4
        for (int kk = 0; kk < HID; kk++)
            s += snb[al * HID + kk] * Wout[kk * NACT + j];
        out[((long)blockIdx.x * 2 + al) * NACT + j] = s;
    }
}

// =================================================================
extern "C" void kernel_launch(void* const* d_in, const int* in_sizes, int n_in,
                              void* d_out, int out_size)
{
    const float* obs  = (const float*)d_in[0];
    const float* bel  = (const float*)d_in[1];
    const float* W1   = (const float*)d_in[2];
    const float* b1   = (const float*)d_in[3];
    const float* W2   = (const float*)d_in[4];
    const float* b2   = (const float*)d_in[5];
    const float* Wb   = (const float*)d_in[6];
    const float* bb   = (const float*)d_in[7];
    const float* Wg   = (const float*)d_in[8];
    const float* bg   = (const float*)d_in[9];
    const float* Wir  = (const float*)d_in[10];
    const float* Wiz  = (const float*)d_in[11];
    const float* Win  = (const float*)d_in[12];
    const float* Whr  = (const float*)d_in[13];
    const float* bhr  = (const float*)d_in[14];
    const float* Whz  = (const float*)d_in[15];
    const float* bhz  = (const float*)d_in[16];
    const float* Whn  = (const float*)d_in[17];
    const float* bhn  = (const float*)d_in[18];
    const float* Wout = (const float*)d_in[19];
    const float* bout = (const float*)d_in[20];
    float* out = (float*)d_out;

    float *h1, *bp, *cat, *gin, *rr, *zz, *gn, *hn, *Op, *lp;
    cudaGetSymbolAddress((void**)&h1,  g_h1);
    cudaGetSymbolAddress((void**)&bp,  g_bp);
    cudaGetSymbolAddress((void**)&cat, g_cat);
    cudaGetSymbolAddress((void**)&gin, g_gruin);
    cudaGetSymbolAddress((void**)&rr,  g_r);
    cudaGetSymbolAddress((void**)&zz,  g_z);
    cudaGetSymbolAddress((void**)&gn,  g_gn);
    cudaGetSymbolAddress((void**)&hn,  g_hn);
    cudaGetSymbolAddress((void**)&Op,  g_Opart);
    cudaGetSymbolAddress((void**)&lp,  g_lpart);

    const int ATT_SMEM  = (128 * SST + 64 * SST + 64 * SST + 128 * SST) * 4; // 102 KB
    const int GEMM_SMEM = 4 * 64 * SST * 4;                                  // ~68 KB
    cudaFuncSetAttribute(attn_kernel,
                         cudaFuncAttributeMaxDynamicSharedMemorySize, ATT_SMEM);
    cudaFuncSetAttribute(gemm3_kernel<0>,
                         cudaFuncAttributeMaxDynamicSharedMemorySize, GEMM_SMEM);
    cudaFuncSetAttribute(gemm3_kernel<1>,
                         cudaFuncAttributeMaxDynamicSharedMemorySize, GEMM_SMEM);
    cudaFuncSetAttribute(gemm3_kernel<2>,
                         cudaFuncAttributeMaxDynamicSharedMemorySize, GEMM_SMEM);

    const dim3 blk(256);
    const dim3 g64(N_AGENTS / 64, 1);    // N=64 outputs
    const dim3 g128(N_AGENTS / 64, 2);   // N=128 outputs

    // h1 = relu(obs@W1 + b1)
    gemm3_kernel<1><<<g64, blk, GEMM_SMEM>>>(obs, OBS_D, W1, EMB, OBS_D,
                                             nullptr, 0, nullptr, 0, 0, b1, h1, EMB);
    // h_obs = relu(h1@W2 + b2) -> g_cat cols [0..63]
    gemm3_kernel<1><<<g64, blk, GEMM_SMEM>>>(h1, EMB, W2, EMB, EMB,
                                             nullptr, 0, nullptr, 0, 0, b2, cat, HID);
    // bp = beliefs@Wb + bb
    gemm3_kernel<0><<<g64, blk, GEMM_SMEM>>>(bel, HID, Wb, EMB, HID,
                                             nullptr, 0, nullptr, 0, 0, bb, bp, EMB);
    // attention: tf32 mma flash partials (16-way key split) + merge
    attn_kernel<<<dim3(N_AGENTS / 128, NSPLIT), blk, ATT_SMEM>>>(bp, Op, lp);
    attn_merge_kernel<<<(N_AGENTS * EMB) / 256, blk>>>(Op, lp, cat);
    // gru_in = cat@Wg + bg
    gemm3_kernel<0><<<g128, blk, GEMM_SMEM>>>(cat, HID, Wg, HID, HID,
                                              nullptr, 0, nullptr, 0, 0, bg, gin, HID);
    // r = sigmoid(gin@Wir + bel@Whr + bhr)
    gemm3_kernel<2><<<g128, blk, GEMM_SMEM>>>(gin, HID, Wir, HID, HID,
                                              bel, HID, Whr, HID, HID, bhr, rr, HID);
    // z = sigmoid(gin@Wiz + bel@Whz + bhz)
    gemm3_kernel<2><<<g128, blk, GEMM_SMEM>>>(gin, HID, Wiz, HID, HID,
                                              bel, HID, Whz, HID, HID, bhz, zz, HID);
    // gn = gin@Win
    gemm3_kernel<0><<<g128, blk, GEMM_SMEM>>>(gin, HID, Win, HID, HID,
                                              nullptr, 0, nullptr, 0, 0, nullptr, gn, HID);
    // hn = bel@Whn + bhn
    gemm3_kernel<0><<<g128, blk, GEMM_SMEM>>>(bel, HID, Whn, HID, HID,
                                              nullptr, 0, nullptr, 0, 0, bhn, hn, HID);
    // combine + logits
    combine_kernel<<<N_AGENTS / 2, blk>>>(gn, hn, rr, zz, bel, Wout, bout, out);
}